// round 14
// baseline (speedup 1.0000x reference)
#include <cuda_runtime.h>
#include <cuda_bf16.h>
#include <cstdint>

// Problem constants (fixed shapes)
#define BT    16384      // B*T
#define HID   512
#define NP    30
#define NU    600
#define NA    80
#define NK    10

// Pre-split W, transposed n-major: [n][k], n padded 30->32 with zeros.
__device__ __nv_bfloat16 g_wh[32 * HID];
__device__ __nv_bfloat16 g_wl[32 * HID];

__device__ __forceinline__ uint32_t smem_u32(const void* p) {
    return (uint32_t)__cvta_generic_to_shared(p);
}
__device__ __forceinline__ void ldsm_x4(uint32_t& r0, uint32_t& r1,
                                        uint32_t& r2, uint32_t& r3, uint32_t addr) {
    asm volatile("ldmatrix.sync.aligned.m8n8.x4.shared.b16 {%0,%1,%2,%3}, [%4];"
                 : "=r"(r0), "=r"(r1), "=r"(r2), "=r"(r3) : "r"(addr));
}
__device__ __forceinline__ void ldsm_x2(uint32_t& r0, uint32_t& r1, uint32_t addr) {
    asm volatile("ldmatrix.sync.aligned.m8n8.x2.shared.b16 {%0,%1}, [%2];"
                 : "=r"(r0), "=r"(r1) : "r"(addr));
}
__device__ __forceinline__ void mma_bf16(float* c, const uint32_t* a,
                                         uint32_t b0, uint32_t b1) {
    asm volatile(
        "mma.sync.aligned.m16n8k16.row.col.f32.bf16.bf16.f32 "
        "{%0,%1,%2,%3}, {%4,%5,%6,%7}, {%8,%9}, {%0,%1,%2,%3};"
        : "+f"(c[0]), "+f"(c[1]), "+f"(c[2]), "+f"(c[3])
        : "r"(a[0]), "r"(a[1]), "r"(a[2]), "r"(a[3]), "r"(b0), "r"(b1));
}

// ---------------------------------------------------------------------------
// Kernel 0: split W (f32 [512][30]) into bf16 hi/lo, transposed [32][512].
// ---------------------------------------------------------------------------
__global__ __launch_bounds__(256) void k0_wsplit(const float* __restrict__ W)
{
    int idx = blockIdx.x * 256 + threadIdx.x;   // 0..16383
    int n = idx >> 9, k = idx & 511;
    float f = (n < NP) ? W[(size_t)k * NP + n] : 0.f;
    __nv_bfloat16 hi = __float2bfloat16(f);
    __nv_bfloat16 lo = __float2bfloat16(f - __bfloat162float(hi));
    g_wh[idx] = hi;
    g_wl[idx] = lo;
}

// ---------------------------------------------------------------------------
// Fused kernel: 512 CTAs x 32 bt rows, 256 threads (8 warps = 2 mt x 4 n8).
//  Phase A: HMMA GEMM M=32 N=32(pad) K=512, 8 chunks of 64, A and B tiles
//           double-buffered, ONE sync per chunk. 3-term bf16 split
//           (Ah*Wh + Ah*Wl + Al*Wh). B restaged per chunk from pre-split
//           global (pure LDG.128 -> STS.128).
//  Phase B: window for same 32 bt (phi once per (bt,u), charseq rows [0,32)
//           staged, analytic cutoff + global tail). scs/sphi alias A tiles.
// Grid 512 -> ~28 warps/SM: the occupancy the 256-CTA versions couldn't get.
// ---------------------------------------------------------------------------
#define K1T    256
#define MROWS  32
#define CHUNK  64
#define NCH    (HID / CHUNK)   // 8
#define ASTR   72              // smem row stride (bf16): 144B, LDSM-clean
#define TILEB  4608            // 32 rows * 72 * 2B

#define OFF_A    0              // 4 x 4608 (buf0h, buf0l, buf1h, buf1l)
#define OFF_B    18432          // 4 x 4608 (buf0h, buf0l, buf1h, buf1l)
#define OFF_SPAR 36864          // 30*32*4 = 3840
#define OFF_CUT  40704          // 32*4    = 128
#define SMEM_TOT 40832
#define OFF_SCS  0              // 32*80*4 = 10240 (aliases A after GEMM)
#define OFF_SPHI 10240          // 32*33*4 = 4224  (aliases A after GEMM)

__global__ __launch_bounds__(K1T, 3) void k_fused(
    const float* __restrict__ lstm,
    const float* __restrict__ bias,
    const float* __restrict__ charseq,
    float* __restrict__ out)
{
    extern __shared__ __align__(16) char buf[];
    float* spar = reinterpret_cast<float*>(buf + OFF_SPAR);  // [p][bl]

    const int tid = threadIdx.x;
    const int wid = tid >> 5;
    const int lid = tid & 31;
    const int t0  = blockIdx.x * MROWS;
    const int mt  = wid >> 2;          // m16-tile 0..1
    const int nt  = wid & 3;           // n8-tile 0..3
    const uint32_t sbase = smem_u32(buf);

    // ---- A/B staging helpers
    // A chunk: 32 rows x 64 k f32 = 512 float4; 2 per thread.
    float4 va[2];
    auto ldg_a = [&](int ch) {
        #pragma unroll
        for (int j = 0; j < 2; j++) {
            int idx = tid + K1T * j;
            int row = idx >> 4, c4 = idx & 15;
            va[j] = *reinterpret_cast<const float4*>(
                lstm + (size_t)(t0 + row) * HID + ch * CHUNK + c4 * 4);
        }
    };
    // B chunk: 32 n x 64 k bf16 per split = 256 uint4 per split; 1 each.
    uint4 wbh, wbl;
    const int bn = tid >> 3, bg = tid & 7;
    auto ldg_b = [&](int ch) {
        wbh = *reinterpret_cast<const uint4*>(&g_wh[bn * HID + ch * CHUNK + bg * 8]);
        wbl = *reinterpret_cast<const uint4*>(&g_wl[bn * HID + ch * CHUNK + bg * 8]);
    };
    auto sts_chunk = [&](int bsel) {
        __nv_bfloat16* dAh = reinterpret_cast<__nv_bfloat16*>(
            buf + OFF_A + bsel * 2 * TILEB);
        __nv_bfloat16* dAl = reinterpret_cast<__nv_bfloat16*>(
            buf + OFF_A + bsel * 2 * TILEB + TILEB);
        #pragma unroll
        for (int j = 0; j < 2; j++) {
            int idx = tid + K1T * j;
            int row = idx >> 4, c4 = idx & 15;
            float4 x = va[j];
            __nv_bfloat162 h01 = __float22bfloat162_rn(make_float2(x.x, x.y));
            __nv_bfloat162 h23 = __float22bfloat162_rn(make_float2(x.z, x.w));
            float2 f01 = __bfloat1622float2(h01);
            float2 f23 = __bfloat1622float2(h23);
            __nv_bfloat162 l01 = __float22bfloat162_rn(
                make_float2(x.x - f01.x, x.y - f01.y));
            __nv_bfloat162 l23 = __float22bfloat162_rn(
                make_float2(x.z - f23.x, x.w - f23.y));
            *reinterpret_cast<uint2*>(&dAh[row * ASTR + c4 * 4]) =
                make_uint2(*reinterpret_cast<uint32_t*>(&h01),
                           *reinterpret_cast<uint32_t*>(&h23));
            *reinterpret_cast<uint2*>(&dAl[row * ASTR + c4 * 4]) =
                make_uint2(*reinterpret_cast<uint32_t*>(&l01),
                           *reinterpret_cast<uint32_t*>(&l23));
        }
        __nv_bfloat16* dBh = reinterpret_cast<__nv_bfloat16*>(
            buf + OFF_B + bsel * 2 * TILEB);
        __nv_bfloat16* dBl = reinterpret_cast<__nv_bfloat16*>(
            buf + OFF_B + bsel * 2 * TILEB + TILEB);
        *reinterpret_cast<uint4*>(&dBh[bn * ASTR + bg * 8]) = wbh;
        *reinterpret_cast<uint4*>(&dBl[bn * ASTR + bg * 8]) = wbl;
    };

    // ---- prologue: chunk 0
    ldg_a(0);
    ldg_b(0);
    sts_chunk(0);
    __syncthreads();

    // ======================= Phase A mainloop =======================
    float acc[4];
    #pragma unroll
    for (int j = 0; j < 4; j++) acc[j] = 0.f;

    // ldmatrix lane addresses (fixed per thread)
    const uint32_t aoff = (uint32_t)((mt * 16 + (lid & 15)) * ASTR +
                                     ((lid & 16) ? 8 : 0)) * 2;
    const int l15 = lid & 15;
    const uint32_t boff = (uint32_t)((nt * 8 + (l15 & 7)) * ASTR +
                                     ((l15 & 8) ? 8 : 0)) * 2;

    #pragma unroll 2
    for (int ch = 0; ch < NCH; ch++) {
        if (ch + 1 < NCH) { ldg_a(ch + 1); ldg_b(ch + 1); }

        const uint32_t aH = sbase + OFF_A + (uint32_t)((ch & 1) * 2 * TILEB) + aoff;
        const uint32_t aL = aH + TILEB;
        const uint32_t bH = sbase + OFF_B + (uint32_t)((ch & 1) * 2 * TILEB) + boff;
        const uint32_t bL = bH + TILEB;
        #pragma unroll
        for (int ks = 0; ks < 4; ks++) {
            uint32_t koff = (uint32_t)(ks * 16) * 2;
            uint32_t ah[4], al[4], bh0, bh1, bl0, bl1;
            ldsm_x4(ah[0], ah[1], ah[2], ah[3], aH + koff);
            ldsm_x4(al[0], al[1], al[2], al[3], aL + koff);
            ldsm_x2(bh0, bh1, bH + koff);
            ldsm_x2(bl0, bl1, bL + koff);
            mma_bf16(acc, ah, bh0, bh1);
            mma_bf16(acc, ah, bl0, bl1);
            mma_bf16(acc, al, bh0, bh1);
        }

        if (ch + 1 < NCH) sts_chunk((ch + 1) & 1);
        __syncthreads();
    }

    // epilogue: +bias, exp, negate b-block, params -> spar[p][bl]
    {
        const int tl = mt * 16 + (lid >> 2);
        const int pb = nt * 8 + (lid & 3) * 2;
        #pragma unroll
        for (int half = 0; half < 2; half++) {
            #pragma unroll
            for (int dp = 0; dp < 2; dp++) {
                int p = pb + dp;
                if (p < NP) {
                    float e = expf(acc[half * 2 + dp] + bias[p]);
                    if (p >= NK && p < 2 * NK) e = -e;
                    spar[p * MROWS + tl + half * 8] = e;
                }
            }
        }
    }
    __syncthreads();   // spar complete; A region now free for scs/sphi

    // ======================= Phase B: window =======================
    float* scs  = reinterpret_cast<float*>(buf + OFF_SCS);   // [32][80]
    float* sphi = reinterpret_cast<float*>(buf + OFF_SPHI);  // [32][33]
    int*   scut = reinterpret_cast<int*>(buf + OFF_CUT);     // [32]

    const int b = t0 >> 10;
    const float* cbase = charseq + (size_t)b * NU * NA;

    // stage charseq rows [0,32): 640 float4
    {
        const float4* cb4 = reinterpret_cast<const float4*>(cbase);
        float4* scs4 = reinterpret_cast<float4*>(scs);
        #pragma unroll
        for (int j = 0; j < 3; j++) {
            int idx = tid + K1T * j;
            if (idx < 32 * (NA / 4)) scs4[idx] = cb4[idx];
        }
    }

    const int bl  = tid >> 3;   // bt_local 0..31
    const int sub = tid & 7;    // 8 subs

    // phi: thread (bl, sub) covers u = sub + 8r, r < 4
    {
        float a[NK], nb[NK], kk[NK];
        #pragma unroll
        for (int k = 0; k < NK; k++) {
            a[k]  = spar[k * MROWS + bl];
            nb[k] = spar[(NK + k) * MROWS + bl];      // -b_k
            kk[k] = spar[(2 * NK + k) * MROWS + bl];
        }
        // u > kappa + sqrt(48/b): term < exp(-48) -> truncate
        float cut = 1.f;
        #pragma unroll
        for (int k = 0; k < NK; k++)
            cut = fmaxf(cut, kk[k] + __fsqrt_rn(__fdividef(48.f, -nb[k])));
        int ucut = min(NU, (int)cut + 1);
        if (sub == 0) scut[bl] = ucut;
        #pragma unroll
        for (int r = 0; r < 4; r++) {
            int u = sub + 8 * r;
            if (u < ucut) {
                float uf  = (float)u;
                float phi = 0.f;
                #pragma unroll
                for (int k = 0; k < NK; k++) {
                    float d = kk[k] - uf;
                    phi += a[k] * __expf(nb[k] * d * d);
                }
                sphi[bl * 33 + u] = phi;
            }
        }
    }
    __syncthreads();

    // accumulate: thread (bl, sub) owns a-cols [sub*10, sub*10+10)
    {
        const int ucut = scut[bl];
        const int uend = min(ucut, 32);

        float acc2[10];
        #pragma unroll
        for (int j = 0; j < 10; j++) acc2[j] = 0.f;

        for (int u = 0; u < uend; u++) {
            float phi = sphi[bl * 33 + u];
            const float* r = scs + u * NA + sub * 10;
            #pragma unroll
            for (int j = 0; j < 5; j++) {
                float2 c = *reinterpret_cast<const float2*>(r + 2 * j);
                acc2[2 * j + 0] = fmaf(phi, c.x, acc2[2 * j + 0]);
                acc2[2 * j + 1] = fmaf(phi, c.y, acc2[2 * j + 1]);
            }
        }
        // tail u >= 32 (analytically unreachable; correctness fallback)
        if (ucut > 32) {
            float a[NK], nb[NK], kk[NK];
            #pragma unroll
            for (int k = 0; k < NK; k++) {
                a[k]  = spar[k * MROWS + bl];
                nb[k] = spar[(NK + k) * MROWS + bl];
                kk[k] = spar[(2 * NK + k) * MROWS + bl];
            }
            for (int u = 32; u < ucut; u++) {
                float uf  = (float)u;
                float phi = 0.f;
                #pragma unroll
                for (int k = 0; k < NK; k++) {
                    float d = kk[k] - uf;
                    phi += a[k] * __expf(nb[k] * d * d);
                }
                const float* r = cbase + (size_t)u * NA + sub * 10;
                #pragma unroll
                for (int j = 0; j < 10; j++)
                    acc2[j] = fmaf(phi, __ldg(r + j), acc2[j]);
            }
        }

        float2* op = reinterpret_cast<float2*>(
            out + (size_t)(t0 + bl) * NA + sub * 10);
        #pragma unroll
        for (int j = 0; j < 5; j++)
            op[j] = make_float2(acc2[2 * j], acc2[2 * j + 1]);
    }
}

// ---------------------------------------------------------------------------
extern "C" void kernel_launch(void* const* d_in, const int* in_sizes, int n_in,
                              void* d_out, int out_size)
{
    const float* lstm = (const float*)d_in[0];   // [16,1024,512]
    const float* cs   = (const float*)d_in[1];   // [16,600,80]
    const float* W    = (const float*)d_in[2];   // [512,30]
    const float* bias = (const float*)d_in[3];   // [30]
    float* out = (float*)d_out;                  // [16,1024,80]

    (void)in_sizes; (void)n_in; (void)out_size;

    static int smem_set = 0;
    if (!smem_set) {
        cudaFuncSetAttribute(k_fused,
                             cudaFuncAttributeMaxDynamicSharedMemorySize,
                             SMEM_TOT);
        smem_set = 1;
    }
    k0_wsplit<<<64, 256>>>(W);
    k_fused<<<BT / MROWS, K1T, SMEM_TOT>>>(lstm, bias, cs, out);
}

// round 15
// speedup vs baseline: 1.0217x; 1.0217x over previous
#include <cuda_runtime.h>
#include <cuda_bf16.h>
#include <cstdint>

// Problem constants (fixed shapes)
#define BT    16384      // B*T
#define HID   512
#define NP    30
#define NU    600
#define NA    80
#define NK    10

// Scratch: transposed exp'ed params [p][bt].
__device__ float g_par[NP * BT];
// Pre-split W, transposed n-major: [n][k], n padded 30->32 with zeros.
__device__ __nv_bfloat16 g_wh[32 * HID];
__device__ __nv_bfloat16 g_wl[32 * HID];

__device__ __forceinline__ uint32_t smem_u32(const void* p) {
    return (uint32_t)__cvta_generic_to_shared(p);
}
__device__ __forceinline__ void ldsm_x4(uint32_t& r0, uint32_t& r1,
                                        uint32_t& r2, uint32_t& r3, uint32_t addr) {
    asm volatile("ldmatrix.sync.aligned.m8n8.x4.shared.b16 {%0,%1,%2,%3}, [%4];"
                 : "=r"(r0), "=r"(r1), "=r"(r2), "=r"(r3) : "r"(addr));
}
__device__ __forceinline__ void ldsm_x2(uint32_t& r0, uint32_t& r1, uint32_t addr) {
    asm volatile("ldmatrix.sync.aligned.m8n8.x2.shared.b16 {%0,%1}, [%2];"
                 : "=r"(r0), "=r"(r1) : "r"(addr));
}
__device__ __forceinline__ void mma_bf16(float* c, const uint32_t* a,
                                         uint32_t b0, uint32_t b1) {
    asm volatile(
        "mma.sync.aligned.m16n8k16.row.col.f32.bf16.bf16.f32 "
        "{%0,%1,%2,%3}, {%4,%5,%6,%7}, {%8,%9}, {%0,%1,%2,%3};"
        : "+f"(c[0]), "+f"(c[1]), "+f"(c[2]), "+f"(c[3])
        : "r"(a[0]), "r"(a[1]), "r"(a[2]), "r"(a[3]), "r"(b0), "r"(b1));
}
__device__ __forceinline__ void split_bf16(float f, __nv_bfloat16& hi, __nv_bfloat16& lo) {
    hi = __float2bfloat16(f);
    lo = __float2bfloat16(f - __bfloat162float(hi));
}

// ---------------------------------------------------------------------------
// Kernel 0: split W into bf16 hi/lo transposed [32][512]. COALESCED linear
// float4 reads (was stride-120B scalar LDGs). Grid 16: blocks 0-14 convert,
// block 15 zeroes pad rows n=30,31.
// ---------------------------------------------------------------------------
__global__ __launch_bounds__(256) void k0_wsplit(const float* __restrict__ W)
{
    int tid = threadIdx.x;
    if (blockIdx.x < 15) {
        int i4 = blockIdx.x * 256 + tid;          // 0..3839
        float4 v = reinterpret_cast<const float4*>(W)[i4];
        float vals[4] = {v.x, v.y, v.z, v.w};
        int e0 = i4 * 4;
        #pragma unroll
        for (int s = 0; s < 4; s++) {
            int ee = e0 + s;
            int k  = ee / 30;
            int n  = ee - k * 30;
            __nv_bfloat16 hi, lo;
            split_bf16(vals[s], hi, lo);
            g_wh[n * HID + k] = hi;
            g_wl[n * HID + k] = lo;
        }
    } else {
        #pragma unroll
        for (int j = 0; j < 4; j++) {
            int idx = tid + 256 * j;              // 0..1023
            int n = 30 + (idx & 1), k = idx >> 1;
            g_wh[n * HID + k] = __float2bfloat16(0.f);
            g_wl[n * HID + k] = __float2bfloat16(0.f);
        }
    }
}

// ---------------------------------------------------------------------------
// Kernel 1 (verbatim R10, measured ~9.2us): params = lstm @ W + bias -> exp
// -> g_par transposed. 256 CTAs x 64 t; 128 threads (4 warps x m16 x n32).
// ---------------------------------------------------------------------------
#define K1T    128
#define MROWS  64
#define CHUNK  64
#define NCH    (HID / CHUNK)   // 8
#define ASTR   72              // smem row stride (bf16): 144B, LDSM-clean

__global__ __launch_bounds__(K1T) void k1_hmma(
    const float* __restrict__ lstm,
    const float* __restrict__ bias)
{
    __shared__ __align__(16) __nv_bfloat16 sAh[MROWS * ASTR];
    __shared__ __align__(16) __nv_bfloat16 sAl[MROWS * ASTR];
    __shared__ __align__(16) __nv_bfloat16 sBh[32 * ASTR];
    __shared__ __align__(16) __nv_bfloat16 sBl[32 * ASTR];

    const int tid = threadIdx.x;
    const int wid = tid >> 5;
    const int lid = tid & 31;
    const int t0  = blockIdx.x * MROWS;
    const int m0  = wid * 16;

    float acc[4][4];
    #pragma unroll
    for (int n = 0; n < 4; n++)
        #pragma unroll
        for (int j = 0; j < 4; j++) acc[n][j] = 0.f;

    const int a_row = m0 + (lid & 15);
    const int a_c8  = (lid & 16) ? 8 : 0;
    const uint32_t aBh = smem_u32(sAh) + (uint32_t)(a_row * ASTR + a_c8) * 2;
    const uint32_t aBl = smem_u32(sAl) + (uint32_t)(a_row * ASTR + a_c8) * 2;
    const int b_k8  = (lid & 8) ? 8 : 0;
    const int b_n   = (lid & 7) + ((lid & 16) ? 8 : 0);
    const uint32_t bBh = smem_u32(sBh) + (uint32_t)(b_n * ASTR + b_k8) * 2;
    const uint32_t bBl = smem_u32(sBl) + (uint32_t)(b_n * ASTR + b_k8) * 2;

    const int wn0 = tid >> 3, wk0 = (tid & 7) * 8;
    const int wn1 = (tid + K1T) >> 3, wk1 = ((tid + K1T) & 7) * 8;

    float4 va[8];
    uint4  wh0, wh1, wl0, wl1;
    #pragma unroll
    for (int j = 0; j < 8; j++) {
        int idx = tid + K1T * j;
        int row = idx >> 4, c4 = idx & 15;
        va[j] = *reinterpret_cast<const float4*>(
            lstm + (size_t)(t0 + row) * HID + c4 * 4);
    }
    wh0 = *reinterpret_cast<const uint4*>(&g_wh[wn0 * HID + wk0]);
    wh1 = *reinterpret_cast<const uint4*>(&g_wh[wn1 * HID + wk1]);
    wl0 = *reinterpret_cast<const uint4*>(&g_wl[wn0 * HID + wk0]);
    wl1 = *reinterpret_cast<const uint4*>(&g_wl[wn1 * HID + wk1]);

    #pragma unroll 1
    for (int ch = 0; ch < NCH; ch++) {
        __syncthreads();
        #pragma unroll
        for (int j = 0; j < 8; j++) {
            int idx = tid + K1T * j;
            int row = idx >> 4, c4 = idx & 15;
            float4 v = va[j];
            __nv_bfloat162 h01 = __float22bfloat162_rn(make_float2(v.x, v.y));
            __nv_bfloat162 h23 = __float22bfloat162_rn(make_float2(v.z, v.w));
            float2 f01 = __bfloat1622float2(h01);
            float2 f23 = __bfloat1622float2(h23);
            __nv_bfloat162 l01 = __float22bfloat162_rn(
                make_float2(v.x - f01.x, v.y - f01.y));
            __nv_bfloat162 l23 = __float22bfloat162_rn(
                make_float2(v.z - f23.x, v.w - f23.y));
            *reinterpret_cast<uint2*>(&sAh[row * ASTR + c4 * 4]) =
                make_uint2(*reinterpret_cast<uint32_t*>(&h01),
                           *reinterpret_cast<uint32_t*>(&h23));
            *reinterpret_cast<uint2*>(&sAl[row * ASTR + c4 * 4]) =
                make_uint2(*reinterpret_cast<uint32_t*>(&l01),
                           *reinterpret_cast<uint32_t*>(&l23));
        }
        *reinterpret_cast<uint4*>(&sBh[wn0 * ASTR + wk0]) = wh0;
        *reinterpret_cast<uint4*>(&sBh[wn1 * ASTR + wk1]) = wh1;
        *reinterpret_cast<uint4*>(&sBl[wn0 * ASTR + wk0]) = wl0;
        *reinterpret_cast<uint4*>(&sBl[wn1 * ASTR + wk1]) = wl1;
        __syncthreads();

        if (ch + 1 < NCH) {
            int k0 = (ch + 1) * CHUNK;
            #pragma unroll
            for (int j = 0; j < 8; j++) {
                int idx = tid + K1T * j;
                int row = idx >> 4, c4 = idx & 15;
                va[j] = *reinterpret_cast<const float4*>(
                    lstm + (size_t)(t0 + row) * HID + k0 + c4 * 4);
            }
            wh0 = *reinterpret_cast<const uint4*>(&g_wh[wn0 * HID + k0 + wk0]);
            wh1 = *reinterpret_cast<const uint4*>(&g_wh[wn1 * HID + k0 + wk1]);
            wl0 = *reinterpret_cast<const uint4*>(&g_wl[wn0 * HID + k0 + wk0]);
            wl1 = *reinterpret_cast<const uint4*>(&g_wl[wn1 * HID + k0 + wk1]);
        }

        #pragma unroll
        for (int ks = 0; ks < 4; ks++) {
            uint32_t koff = (uint32_t)(ks * 16) * 2;
            uint32_t ah[4], al[4];
            ldsm_x4(ah[0], ah[1], ah[2], ah[3], aBh + koff);
            ldsm_x4(al[0], al[1], al[2], al[3], aBl + koff);
            #pragma unroll
            for (int pr = 0; pr < 2; pr++) {
                uint32_t poff = (uint32_t)(pr * 16 * ASTR) * 2 + koff;
                uint32_t bh[4], bl[4];
                ldsm_x4(bh[0], bh[1], bh[2], bh[3], bBh + poff);
                ldsm_x4(bl[0], bl[1], bl[2], bl[3], bBl + poff);
                mma_bf16(acc[2 * pr],     ah, bh[0], bh[1]);
                mma_bf16(acc[2 * pr],     ah, bl[0], bl[1]);
                mma_bf16(acc[2 * pr],     al, bh[0], bh[1]);
                mma_bf16(acc[2 * pr + 1], ah, bh[2], bh[3]);
                mma_bf16(acc[2 * pr + 1], ah, bl[2], bl[3]);
                mma_bf16(acc[2 * pr + 1], al, bh[2], bh[3]);
            }
        }
    }

    const int g  = lid >> 2;
    const int tg = lid & 3;
    #pragma unroll
    for (int nt = 0; nt < 4; nt++) {
        int p0 = nt * 8 + tg * 2;
        #pragma unroll
        for (int dp = 0; dp < 2; dp++) {
            int p = p0 + dp;
            if (p < NP) {
                float bz = bias[p];
                float e0 = expf(acc[nt][dp] + bz);
                float e1 = expf(acc[nt][2 + dp] + bz);
                if (p >= NK && p < 2 * NK) { e0 = -e0; e1 = -e1; }
                g_par[p * BT + t0 + m0 + g]     = e0;
                g_par[p * BT + t0 + m0 + g + 8] = e1;
            }
        }
    }
}

// ---------------------------------------------------------------------------
// Kernel 2 (NEW): window as HMMA GEMM.
// out[32bt, 80a] = phi[32bt, 32u] @ cs[32u, 80a], 3-term bf16 hi/lo split.
// phi computed once per (bt,u) with analytic cutoff (zeros beyond); cs rows
// [0,32) converted+TRANSPOSED to [a][u] hi/lo smem. 8 warps = 2 mt x 4 wn;
// warp wn covers n8-tiles {wn, wn+4, wn+8<10}. Tail ucut>32: flag + scalar
// atomicAdd fallback (analytically never taken).
// ---------------------------------------------------------------------------
#define BPB   32
#define PSTR  40    // [bt][u] / [a][u] smem stride in bf16 elems (80B)

__global__ __launch_bounds__(256) void k2_wgemm(
    const float* __restrict__ charseq,
    float* __restrict__ out)
{
    __shared__ float spar[NP * BPB];                         // 3.75 KB
    __shared__ __align__(16) __nv_bfloat16 sPh[BPB * PSTR];  // 2.5 KB
    __shared__ __align__(16) __nv_bfloat16 sPl[BPB * PSTR];
    __shared__ __align__(16) __nv_bfloat16 sCh[NA * PSTR];   // 6.25 KB
    __shared__ __align__(16) __nv_bfloat16 sCl[NA * PSTR];
    __shared__ int scut[BPB];
    __shared__ int sflag;

    const int tid = threadIdx.x;
    const int wid = tid >> 5;
    const int lid = tid & 31;
    const int bt0 = blockIdx.x * BPB;
    const int b   = bt0 >> 10;
    const float* cbase = charseq + (size_t)b * NU * NA;

    if (tid == 0) sflag = 0;

    // batched loads: params (4/thread) + cs rows [0,32) (640 f4, 3/thread)
    float pr[4];
    #pragma unroll
    for (int j = 0; j < 4; j++) {
        int idx = tid + 256 * j;
        if (idx < NP * BPB) {
            int p = idx >> 5, bl = idx & 31;
            pr[j] = g_par[p * BT + bt0 + bl];
        }
    }
    float4 csr[3];
    const float4* cb4 = reinterpret_cast<const float4*>(cbase);
    #pragma unroll
    for (int j = 0; j < 3; j++) {
        int idx = tid + 256 * j;
        if (idx < BPB * (NA / 4)) csr[j] = cb4[idx];
    }
    #pragma unroll
    for (int j = 0; j < 4; j++) {
        int idx = tid + 256 * j;
        if (idx < NP * BPB) spar[idx] = pr[j];
    }
    // cs -> transposed [a][u] hi/lo
    #pragma unroll
    for (int j = 0; j < 3; j++) {
        int idx = tid + 256 * j;
        if (idx < BPB * (NA / 4)) {
            int u  = idx / (NA / 4);
            int a0 = (idx - u * (NA / 4)) * 4;
            float vals[4] = {csr[j].x, csr[j].y, csr[j].z, csr[j].w};
            #pragma unroll
            for (int s = 0; s < 4; s++) {
                __nv_bfloat16 hi, lo;
                split_bf16(vals[s], hi, lo);
                sCh[(a0 + s) * PSTR + u] = hi;
                sCl[(a0 + s) * PSTR + u] = lo;
            }
        }
    }
    __syncthreads();

    // phi -> hi/lo smem [bt][u]; zeros for u >= ucut (covers all u<32)
    {
        const int bl = tid >> 3, sub = tid & 7;
        float a[NK], nb[NK], kk[NK];
        #pragma unroll
        for (int k = 0; k < NK; k++) {
            a[k]  = spar[k * BPB + bl];
            nb[k] = spar[(NK + k) * BPB + bl];     // -b_k
            kk[k] = spar[(2 * NK + k) * BPB + bl];
        }
        // u > kappa + sqrt(48/b): term < exp(-48) -> truncate
        float cut = 1.f;
        #pragma unroll
        for (int k = 0; k < NK; k++)
            cut = fmaxf(cut, kk[k] + __fsqrt_rn(__fdividef(48.f, -nb[k])));
        int ucut = min(NU, (int)cut + 1);
        if (sub == 0) {
            scut[bl] = ucut;
            if (ucut > BPB) sflag = 1;
        }
        #pragma unroll
        for (int r = 0; r < 4; r++) {
            int u = sub + 8 * r;
            float phi = 0.f;
            if (u < ucut) {
                float uf = (float)u;
                #pragma unroll
                for (int k = 0; k < NK; k++) {
                    float d = kk[k] - uf;
                    phi += a[k] * __expf(nb[k] * d * d);
                }
            }
            __nv_bfloat16 hi, lo;
            split_bf16(phi, hi, lo);
            sPh[bl * PSTR + u] = hi;
            sPl[bl * PSTR + u] = lo;
        }
    }
    __syncthreads();

    // GEMM: warp (mt = wid>>2, wn = wid&3); tiles t = wn + 4*ti
    {
        const int mt = wid >> 2, wn = wid & 3;
        const int ntl = (wn < 2) ? 3 : 2;
        const uint32_t aoff = (uint32_t)((mt * 16 + (lid & 15)) * PSTR +
                                         ((lid & 16) ? 8 : 0)) * 2;
        const uint32_t aH = smem_u32(sPh) + aoff;
        const uint32_t aL = smem_u32(sPl) + aoff;
        const int l15 = lid & 15;

        float c[3][4];
        #pragma unroll
        for (int ti = 0; ti < 3; ti++)
            #pragma unroll
            for (int j = 0; j < 4; j++) c[ti][j] = 0.f;

        #pragma unroll
        for (int ks = 0; ks < 2; ks++) {
            uint32_t koff = (uint32_t)(ks * 16) * 2;
            uint32_t ah[4], al[4];
            ldsm_x4(ah[0], ah[1], ah[2], ah[3], aH + koff);
            ldsm_x4(al[0], al[1], al[2], al[3], aL + koff);
            #pragma unroll
            for (int ti = 0; ti < 3; ti++) {
                if (ti < ntl) {
                    int t = wn + 4 * ti;
                    uint32_t boff = (uint32_t)((t * 8 + (l15 & 7)) * PSTR +
                                               ((l15 & 8) ? 8 : 0)) * 2;
                    uint32_t bh0, bh1, bl0, bl1;
                    ldsm_x2(bh0, bh1, smem_u32(sCh) + boff + koff);
                    ldsm_x2(bl0, bl1, smem_u32(sCl) + boff + koff);
                    mma_bf16(c[ti], ah, bh0, bh1);
                    mma_bf16(c[ti], ah, bl0, bl1);
                    mma_bf16(c[ti], al, bh0, bh1);
                }
            }
        }

        // epilogue: f32 stores (float2, 8B-aligned since col is even)
        const int row0 = mt * 16 + (lid >> 2);
        #pragma unroll
        for (int ti = 0; ti < 3; ti++) {
            if (ti < ntl) {
                int t = wn + 4 * ti;
                int col = t * 8 + (lid & 3) * 2;
                *reinterpret_cast<float2*>(&out[(size_t)(bt0 + row0) * NA + col]) =
                    make_float2(c[ti][0], c[ti][1]);
                *reinterpret_cast<float2*>(&out[(size_t)(bt0 + row0 + 8) * NA + col]) =
                    make_float2(c[ti][2], c[ti][3]);
            }
        }
    }

    // tail (ucut > 32): analytically never taken; correctness fallback.
    __syncthreads();
    if (sflag) {
        const int bl = tid >> 3, sub = tid & 7;
        const int ucut = scut[bl];
        if (ucut > BPB) {
            float a[NK], nb[NK], kk[NK];
            #pragma unroll
            for (int k = 0; k < NK; k++) {
                a[k]  = spar[k * BPB + bl];
                nb[k] = spar[(NK + k) * BPB + bl];
                kk[k] = spar[(2 * NK + k) * BPB + bl];
            }
            for (int u = BPB; u < ucut; u++) {
                float uf = (float)u;
                float phi = 0.f;
                #pragma unroll
                for (int k = 0; k < NK; k++) {
                    float d = kk[k] - uf;
                    phi += a[k] * __expf(nb[k] * d * d);
                }
                const float* r = cbase + (size_t)u * NA + sub * 10;
                #pragma unroll
                for (int j = 0; j < 10; j++)
                    atomicAdd(&out[(size_t)(bt0 + bl) * NA + sub * 10 + j],
                              phi * __ldg(r + j));
            }
        }
    }
}

// ---------------------------------------------------------------------------
extern "C" void kernel_launch(void* const* d_in, const int* in_sizes, int n_in,
                              void* d_out, int out_size)
{
    const float* lstm = (const float*)d_in[0];   // [16,1024,512]
    const float* cs   = (const float*)d_in[1];   // [16,600,80]
    const float* W    = (const float*)d_in[2];   // [512,30]
    const float* bias = (const float*)d_in[3];   // [30]
    float* out = (float*)d_out;                  // [16,1024,80]

    (void)in_sizes; (void)n_in; (void)out_size;

    k0_wsplit<<<16, 256>>>(W);
    k1_hmma<<<BT / MROWS, K1T>>>(lstm, bias);
    k2_wgemm<<<BT / BPB, 256>>>(cs, out);
}